// round 4
// baseline (speedup 1.0000x reference)
#include <cuda_runtime.h>
#include <cstdint>

// Overlap-add reconstruction as a pure gather.
//
// x: [B=16, FV=2000, FRAME=2048] fp32
// out: [B, FV*HOP = 1024000] fp32
//
// Padded output position p = o + PAD0 receives contributions from frames
// f in {q-3..q} clamped to [0, FV-1], where q = p / HOP, at offset p - f*HOP.
// Normalization = 1 / (#valid frames). All accesses float4-vectorized:
// PAD0 % 4 == 0 and HOP % 4 == 0 guarantee a 4-wide output chunk stays
// within one hop cell (same q, same validity, aligned 16B loads).

namespace {
constexpr int B      = 16;
constexpr int FV     = 2000;
constexpr int FRAME  = 2048;
constexpr int HOP    = 512;
constexpr int PAD0   = (FRAME - HOP) / 2;          // 768
constexpr int OUT_PER_B   = FV * HOP;              // 1,024,000
constexpr int VEC_PER_B   = OUT_PER_B / 4;         // 256,000
constexpr int THREADS     = 256;
constexpr int BLOCKS_X    = VEC_PER_B / THREADS;   // 1000 (exact)
}

__global__ __launch_bounds__(THREADS)
void overlap_add_gather(const float* __restrict__ x, float* __restrict__ out) {
    const int vi = blockIdx.x * THREADS + threadIdx.x;   // float4 index within batch
    const int b  = blockIdx.y;

    const int o = vi << 2;                 // output sample index (multiple of 4)
    const int p = o + PAD0;                // padded position
    const int q = p >> 9;                  // p / HOP
    // offset within frame q: p - q*HOP = p & 511 (multiple of 4)

    const float* __restrict__ xb = x + (size_t)b * (size_t)(FV * FRAME);

    float4 acc = make_float4(0.f, 0.f, 0.f, 0.f);
    int cnt = 0;

    // Front-batch the (up to) 4 independent 16B loads for MLP.
    float4 v[4];
    bool   ok[4];
#pragma unroll
    for (int k = 0; k < 4; ++k) {
        const int f = q - k;
        ok[k] = (f >= 0) && (f < FV);
        if (ok[k]) {
            const int t = p - f * HOP;     // in [0, FRAME-4], multiple of 4
            v[k] = *reinterpret_cast<const float4*>(xb + (size_t)f * FRAME + t);
        }
    }
#pragma unroll
    for (int k = 0; k < 4; ++k) {
        if (ok[k]) {
            acc.x += v[k].x; acc.y += v[k].y; acc.z += v[k].z; acc.w += v[k].w;
            ++cnt;
        }
    }

    const float s = 1.0f / (float)cnt;     // cnt >= 2 always within trimmed range
    acc.x *= s; acc.y *= s; acc.z *= s; acc.w *= s;

    float4* __restrict__ ob = reinterpret_cast<float4*>(out) + (size_t)b * VEC_PER_B;
    ob[vi] = acc;
}

extern "C" void kernel_launch(void* const* d_in, const int* in_sizes, int n_in,
                              void* d_out, int out_size) {
    (void)in_sizes; (void)n_in; (void)out_size;
    const float* x = (const float*)d_in[0];
    float* out = (float*)d_out;

    dim3 grid(BLOCKS_X, B, 1);
    overlap_add_gather<<<grid, THREADS>>>(x, out);
}

// round 5
// speedup vs baseline: 1.0032x; 1.0032x over previous
#include <cuda_runtime.h>
#include <cstdint>

// Overlap-add reconstruction as a pure gather (R5: 2 chunks/thread, warp-uniform
// fast path, streaming cache ops).
//
// x:   [B=16, FV=2000, FRAME=2048] fp32
// out: [B, FV*HOP = 1024000] fp32
//
// Padded position p = o + PAD0 sums frames f in {q-3..q} clamped to [0,FV),
// q = p >> 9, each at element address  xb + p + f*(FRAME-HOP) = xb + p + f*1536.
// Normalization = 1/#valid. Interior (q in [3, FV-1]) is branch-free with
// scale 0.25; only ~0.2% of warps (batch edges) take the checked path.
//
// Each thread processes two float4 output vectors offset by THREADS so every
// LDG.128 / STG.128 in a warp is fully coalesced, and all 8 loads are
// front-batched for memory-level parallelism.

namespace {
constexpr int B         = 16;
constexpr int FV        = 2000;
constexpr int FRAME     = 2048;
constexpr int HOP       = 512;
constexpr int PAD0      = (FRAME - HOP) / 2;        // 768
constexpr int STRIDE    = FRAME - HOP;              // 1536 (per-frame addr stride)
constexpr int OUT_PER_B = FV * HOP;                 // 1,024,000 floats
constexpr int VEC_PER_B = OUT_PER_B / 4;            // 256,000 float4
constexpr int THREADS   = 256;
constexpr int V_PER_BLK = 2 * THREADS;              // 512 float4 per block
constexpr int BLOCKS_X  = VEC_PER_B / V_PER_BLK;    // 500 (exact)
}

__device__ __forceinline__ float4 ld_cs_f4(const float* p) {
    return __ldcs(reinterpret_cast<const float4*>(p));
}

__device__ __forceinline__ void sum4_scale(const float4* v, float s, float4& a) {
    a.x = (v[0].x + v[1].x + v[2].x + v[3].x) * s;
    a.y = (v[0].y + v[1].y + v[2].y + v[3].y) * s;
    a.z = (v[0].z + v[1].z + v[2].z + v[3].z) * s;
    a.w = (v[0].w + v[1].w + v[2].w + v[3].w) * s;
}

// Edge-safe path for one float4 chunk (frame validity checks + count scale).
__device__ __forceinline__ float4 gather_edge(const float* __restrict__ base,
                                              int q) {
    float4 acc = make_float4(0.f, 0.f, 0.f, 0.f);
    int cnt = 0;
#pragma unroll
    for (int k = 0; k < 4; ++k) {
        const int f = q - k;
        if (f >= 0 && f < FV) {
            const float4 t = ld_cs_f4(base - k * STRIDE);
            acc.x += t.x; acc.y += t.y; acc.z += t.z; acc.w += t.w;
            ++cnt;
        }
    }
    const float s = 1.0f / (float)cnt;   // cnt >= 2 within the trimmed range
    acc.x *= s; acc.y *= s; acc.z *= s; acc.w *= s;
    return acc;
}

__global__ __launch_bounds__(THREADS)
void overlap_add_gather2(const float* __restrict__ x, float* __restrict__ out) {
    const int tid   = threadIdx.x;
    const int b     = blockIdx.y;
    const int vbase = blockIdx.x * V_PER_BLK;

    const float* __restrict__ xb = x + (size_t)b * (size_t)(FV * FRAME);
    float4* __restrict__ ob = reinterpret_cast<float4*>(out) + (size_t)b * VEC_PER_B;

    const int vi0 = vbase + tid;            // chunk 0 float4 index
    const int vi1 = vi0 + THREADS;          // chunk 1 float4 index (coalesced)

    const int p0 = (vi0 << 2) + PAD0;
    const int p1 = (vi1 << 2) + PAD0;
    const int q0 = p0 >> 9;
    const int q1 = p1 >> 9;                 // q1 >= q0

    const float* base0 = xb + (size_t)p0 + (size_t)q0 * STRIDE;
    const float* base1 = xb + (size_t)p1 + (size_t)q1 * STRIDE;

    if (q0 >= 3 && q1 < FV) {
        // Interior: all 4 frames valid for both chunks. Front-batch 8 loads.
        float4 v[8];
#pragma unroll
        for (int k = 0; k < 4; ++k) {
            v[k]     = ld_cs_f4(base0 - k * STRIDE);
            v[4 + k] = ld_cs_f4(base1 - k * STRIDE);
        }
        float4 a0, a1;
        sum4_scale(v,     0.25f, a0);
        sum4_scale(v + 4, 0.25f, a1);
        __stcs(ob + vi0, a0);
        __stcs(ob + vi1, a1);
    } else {
        __stcs(ob + vi0, gather_edge(base0, q0));
        __stcs(ob + vi1, gather_edge(base1, q1));
    }
}

extern "C" void kernel_launch(void* const* d_in, const int* in_sizes, int n_in,
                              void* d_out, int out_size) {
    (void)in_sizes; (void)n_in; (void)out_size;
    const float* x = (const float*)d_in[0];
    float* out = (float*)d_out;

    dim3 grid(BLOCKS_X, B, 1);
    overlap_add_gather2<<<grid, THREADS>>>(x, out);
}

// round 6
// speedup vs baseline: 1.0038x; 1.0006x over previous
#include <cuda_runtime.h>
#include <cstdint>

// Overlap-add reconstruction as a pure gather (R6: R5 structure + forced
// 32-reg / high-occupancy via __launch_bounds__, 32-bit index math).
//
// x:   [B=16, FV=2000, FRAME=2048] fp32
// out: [B, FV*HOP = 1024000] fp32
//
// Padded position p = o + PAD0 sums frames f in {q-3..q} clamped to [0,FV),
// q = p >> 9, element address xb + p + f*(FRAME-HOP). Normalization = 1/#valid.
// Interior warps (>99.8%) take a branch-free path with constant 0.25 scale.
// 2 float4 chunks per thread, offset by THREADS for full coalescing; all 8
// 16B loads front-batched for MLP.

namespace {
constexpr int B         = 16;
constexpr int FV        = 2000;
constexpr int FRAME     = 2048;
constexpr int HOP       = 512;
constexpr int PAD0      = (FRAME - HOP) / 2;        // 768
constexpr int STRIDE    = FRAME - HOP;              // 1536
constexpr int OUT_PER_B = FV * HOP;                 // 1,024,000 floats
constexpr int VEC_PER_B = OUT_PER_B / 4;            // 256,000 float4
constexpr int THREADS   = 256;
constexpr int V_PER_BLK = 2 * THREADS;              // 512 float4 per block
constexpr int BLOCKS_X  = VEC_PER_B / V_PER_BLK;    // 500 (exact)
}

__device__ __forceinline__ float4 ld_cs_f4(const float* p) {
    return __ldcs(reinterpret_cast<const float4*>(p));
}

__device__ __forceinline__ float4 sum4_scale(const float4* v, float s) {
    float4 a;
    a.x = (v[0].x + v[1].x + v[2].x + v[3].x) * s;
    a.y = (v[0].y + v[1].y + v[2].y + v[3].y) * s;
    a.z = (v[0].z + v[1].z + v[2].z + v[3].z) * s;
    a.w = (v[0].w + v[1].w + v[2].w + v[3].w) * s;
    return a;
}

// Edge-safe path for one float4 chunk (frame validity checks + count scale).
__device__ __forceinline__ float4 gather_edge(const float* __restrict__ base,
                                              int q) {
    float4 acc = make_float4(0.f, 0.f, 0.f, 0.f);
    int cnt = 0;
#pragma unroll
    for (int k = 0; k < 4; ++k) {
        const int f = q - k;
        if (f >= 0 && f < FV) {
            const float4 t = ld_cs_f4(base - k * STRIDE);
            acc.x += t.x; acc.y += t.y; acc.z += t.z; acc.w += t.w;
            ++cnt;
        }
    }
    const float s = 1.0f / (float)cnt;   // cnt >= 2 within the trimmed range
    acc.x *= s; acc.y *= s; acc.z *= s; acc.w *= s;
    return acc;
}

__global__ __launch_bounds__(THREADS, 8)
void overlap_add_gather3(const float* __restrict__ x, float* __restrict__ out) {
    const int tid   = threadIdx.x;
    const int b     = blockIdx.y;
    const int vbase = blockIdx.x * V_PER_BLK;

    // Per-batch bases formed once in 64-bit; everything else 32-bit.
    const float* __restrict__ xb = x + (size_t)b * (size_t)(FV * FRAME);
    float4* __restrict__ ob = reinterpret_cast<float4*>(out) + (size_t)b * VEC_PER_B;

    const int vi0 = vbase + tid;            // chunk 0 float4 index (< 256000)
    const int vi1 = vi0 + THREADS;          // chunk 1 (coalesced)

    const int p0 = (vi0 << 2) + PAD0;
    const int p1 = (vi1 << 2) + PAD0;
    const int q0 = p0 >> 9;
    const int q1 = p1 >> 9;                 // q1 >= q0

    const float* base0 = xb + (unsigned)(p0 + q0 * STRIDE);
    const float* base1 = xb + (unsigned)(p1 + q1 * STRIDE);

    if (q0 >= 3 && q1 < FV) {
        // Interior: all 4 frames valid for both chunks. Front-batch 8 loads.
        float4 v[8];
#pragma unroll
        for (int k = 0; k < 4; ++k) {
            v[k]     = ld_cs_f4(base0 - k * STRIDE);
            v[4 + k] = ld_cs_f4(base1 - k * STRIDE);
        }
        __stcs(ob + vi0, sum4_scale(v,     0.25f));
        __stcs(ob + vi1, sum4_scale(v + 4, 0.25f));
    } else {
        __stcs(ob + vi0, gather_edge(base0, q0));
        __stcs(ob + vi1, gather_edge(base1, q1));
    }
}

extern "C" void kernel_launch(void* const* d_in, const int* in_sizes, int n_in,
                              void* d_out, int out_size) {
    (void)in_sizes; (void)n_in; (void)out_size;
    const float* x = (const float*)d_in[0];
    float* out = (float*)d_out;

    dim3 grid(BLOCKS_X, B, 1);
    overlap_add_gather3<<<grid, THREADS>>>(x, out);
}